// round 14
// baseline (speedup 1.0000x reference)
#include <cuda_runtime.h>
#include <cuda_bf16.h>
#include <cstdint>

// Problem constants
#define BB    2
#define SS    2048
#define DD    1024
#define HH    16
#define DHh   64
#define FFD   4096
#define BSR   (BB*SS)          // 4096 rows
#define QC    256              // query-chunk rows per attention pass
#define NCHUNK (SS/QC)         // 8

typedef __nv_bfloat16 bf16;

// ---------------- static scratch (~306MB; lifetimes documented) -------------
__device__ float g_V  [BSR*DD];     // V fp32; later aliased as AR (out-proj+res) and Z (ffn2 out)
__device__ float g_scr[BSR*FFD];    // attention: Sc fp32 scores chunk; FFN: bf16 hidden hi/lo pair
__device__ float g_Y  [BSR*DD];     // LN1 output fp32 (residual for FFN2)

__device__ bf16 g_Xh[BSR*DD],  g_Xl[BSR*DD];
__device__ bf16 g_Wqh[DD*DD],  g_Wql[DD*DD];
__device__ bf16 g_Wkh[DD*DD],  g_Wkl[DD*DD];
__device__ bf16 g_Woh[DD*DD],  g_Wol[DD*DD];
__device__ bf16 g_W1h[FFD*DD], g_W1l[FFD*DD];
__device__ bf16 g_W2h[DD*FFD], g_W2l[DD*FFD];
__device__ bf16 g_Qh[BSR*DD],  g_Ql[BSR*DD];
__device__ bf16 g_Kh[BSR*DD],  g_Kl[BSR*DD];
__device__ bf16 g_Vth[BB*HH*DHh*SS], g_Vtl[BB*HH*DHh*SS];
__device__ bf16 g_Sch[BB*HH*QC*SS],  g_Scl[BB*HH*QC*SS];
__device__ bf16 g_CTh[BSR*DD], g_CTl[BSR*DD];
__device__ bf16 g_Yh[BSR*DD],  g_Yl[BSR*DD];

// ---------------- helpers ----------------
__device__ __forceinline__ void bsplit2(float x0, float x1, uint32_t& hp, uint32_t& lp)
{
    asm("cvt.rn.bf16x2.f32 %0, %1, %2;" : "=r"(hp) : "f"(x1), "f"(x0));
    float h0 = __uint_as_float(hp << 16);
    float h1 = __uint_as_float(hp & 0xffff0000u);
    float r0 = x0 - h0;
    float r1 = x1 - h1;
    asm("cvt.rn.bf16x2.f32 %0, %1, %2;" : "=r"(lp) : "f"(r1), "f"(r0));
}

__device__ __forceinline__ void mma16(float* d, const uint32_t* a, const uint32_t* b)
{
    asm volatile(
        "mma.sync.aligned.m16n8k16.row.col.f32.bf16.bf16.f32 "
        "{%0,%1,%2,%3},{%4,%5,%6,%7},{%8,%9},{%0,%1,%2,%3};"
        : "+f"(d[0]), "+f"(d[1]), "+f"(d[2]), "+f"(d[3])
        : "r"(a[0]), "r"(a[1]), "r"(a[2]), "r"(a[3]), "r"(b[0]), "r"(b[1]));
}

__device__ __forceinline__ void cpasync16(uint32_t dst_smem, const void* src)
{
    asm volatile("cp.async.cg.shared.global [%0], [%1], 16;\n"
                 :: "r"(dst_smem), "l"((unsigned long long)(uintptr_t)src)
                 : "memory");
}
__device__ __forceinline__ void cpasync_commit()
{
    asm volatile("cp.async.commit_group;\n" ::: "memory");
}
__device__ __forceinline__ void cpasync_wait_all()
{
    asm volatile("cp.async.wait_group 0;\n" ::: "memory");
}

// ================= bg3: pure bf16-pair NT GEMM, cp.async double-buffered =====
// C = epilogue( alpha * (Ah+Al)[M,K] @ (Bh+Bl)[N,K]^T ), 3-MMA split.
// 512 threads = 16 warps; warp grid (BM/WM)x(BN/WN) == 16. BK == 32.
template<int BM,int BN,int WM,int WN,bool RELU,bool BIAS,bool RES,bool OUTF,bool OUTB>
__global__ __launch_bounds__(512,1)
void bg3(const bf16* __restrict__ Ah, const bf16* __restrict__ Al, int lda,
         const bf16* __restrict__ Bh, const bf16* __restrict__ Bl, int ldb,
         float* __restrict__ Cf, bf16* __restrict__ Ch, bf16* __restrict__ Cl, int ldc,
         int K, float alpha,
         const float* __restrict__ bias, const float* __restrict__ res,
         int zdiv, long soA, long siA, long soB, long siB, long soC, long siC)
{
    constexpr int BK  = 32;
    constexpr int SDP = BK/2 + 4;          // 20 uint32 per row
    constexpr int ASZ = BM * SDP;
    constexpr int BSZ = BN * SDP;
    constexpr int STG = 2*ASZ + 2*BSZ;     // uint32 per stage
    constexpr int MT  = WM / 16;
    constexpr int NT2 = WN / 8;
    constexpr int MW  = BM / WM;
    constexpr int ACH = BM * (BK/8);       // 16B chunks in A tile
    constexpr int BCH = BN * (BK/8);

    extern __shared__ uint32_t sm[];
    const uint32_t smBase = (uint32_t)__cvta_generic_to_shared(sm);

    const int z  = blockIdx.z;
    const long zo = z / zdiv, zi = z % zdiv;
    Ah += zo*soA + zi*siA;  Al += zo*soA + zi*siA;
    Bh += zo*soB + zi*siB;  Bl += zo*soB + zi*siB;
    if (OUTF) Cf += zo*soC + zi*siC;
    if (OUTB) { Ch += zo*soC + zi*siC; Cl += zo*soC + zi*siC; }

    const int tid    = threadIdx.x;
    const int lane   = tid & 31;
    const int warpId = tid >> 5;
    const int wm     = warpId % MW;
    const int wn     = warpId / MW;
    const int r      = lane >> 2;
    const int c      = lane & 3;
    const int rowBase = blockIdx.y * BM;
    const int colBase = blockIdx.x * BN;

    // chunk coords: chunk i covers row i>>2, k-elems (i&3)*8 .. +7
    const int aRow = tid >> 2, aK8 = tid & 3;                 // valid when tid < ACH
    const int bRow = tid >> 2, bK8 = tid & 3;                 // valid when tid < BCH

    float acc[MT][NT2][4];
    #pragma unroll
    for (int im = 0; im < MT; im++)
        #pragma unroll
        for (int in = 0; in < NT2; in++)
            #pragma unroll
            for (int q = 0; q < 4; q++) acc[im][in][q] = 0.f;

    const int nT = K / BK;

    // ---- prologue: issue tile 0 into stage 0 ----
    if (tid < ACH) {
        uint32_t d = smBase + (0*STG + aRow*SDP + aK8*4)*4;
        cpasync16(d,            Ah + (long)(rowBase + aRow)*lda + aK8*8);
        cpasync16(d + ASZ*4,    Al + (long)(rowBase + aRow)*lda + aK8*8);
    }
    if (tid < BCH) {
        uint32_t d = smBase + (0*STG + 2*ASZ + bRow*SDP + bK8*4)*4;
        cpasync16(d,            Bh + (long)(colBase + bRow)*ldb + bK8*8);
        cpasync16(d + BSZ*4,    Bl + (long)(colBase + bRow)*ldb + bK8*8);
    }
    cpasync_commit();

    for (int t = 0; t < nT; t++) {
        cpasync_wait_all();
        __syncthreads();

        if (t + 1 < nT) {
            const int kn = (t + 1) * BK;
            const int st = (t + 1) & 1;
            if (tid < ACH) {
                uint32_t d = smBase + (st*STG + aRow*SDP + aK8*4)*4;
                cpasync16(d,         Ah + (long)(rowBase + aRow)*lda + kn + aK8*8);
                cpasync16(d + ASZ*4, Al + (long)(rowBase + aRow)*lda + kn + aK8*8);
            }
            if (tid < BCH) {
                uint32_t d = smBase + (st*STG + 2*ASZ + bRow*SDP + bK8*4)*4;
                cpasync16(d,         Bh + (long)(colBase + bRow)*ldb + kn + bK8*8);
                cpasync16(d + BSZ*4, Bl + (long)(colBase + bRow)*ldb + kn + bK8*8);
            }
            cpasync_commit();
        }

        const uint32_t* pAh = sm + (t & 1)*STG;
        const uint32_t* pAl = pAh + ASZ;
        const uint32_t* pBh = pAh + 2*ASZ;
        const uint32_t* pBl = pBh + BSZ;

        #pragma unroll
        for (int ks = 0; ks < BK/16; ks++) {
            const int pb = ks * 8;
            uint32_t afh[MT][4], afl[MT][4], bfh[NT2][2], bfl[NT2][2];
            #pragma unroll
            for (int im = 0; im < MT; im++) {
                const int mb = wm*WM + im*16;
                afh[im][0] = pAh[(mb+r  )*SDP + pb + c    ];
                afh[im][1] = pAh[(mb+r+8)*SDP + pb + c    ];
                afh[im][2] = pAh[(mb+r  )*SDP + pb + c + 4];
                afh[im][3] = pAh[(mb+r+8)*SDP + pb + c + 4];
                afl[im][0] = pAl[(mb+r  )*SDP + pb + c    ];
                afl[im][1] = pAl[(mb+r+8)*SDP + pb + c    ];
                afl[im][2] = pAl[(mb+r  )*SDP + pb + c + 4];
                afl[im][3] = pAl[(mb+r+8)*SDP + pb + c + 4];
            }
            #pragma unroll
            for (int in = 0; in < NT2; in++) {
                const int nb = wn*WN + in*8;
                bfh[in][0] = pBh[(nb+r)*SDP + pb + c    ];
                bfh[in][1] = pBh[(nb+r)*SDP + pb + c + 4];
                bfl[in][0] = pBl[(nb+r)*SDP + pb + c    ];
                bfl[in][1] = pBl[(nb+r)*SDP + pb + c + 4];
            }
            #pragma unroll
            for (int im = 0; im < MT; im++)
                #pragma unroll
                for (int in = 0; in < NT2; in++) {
                    mma16(acc[im][in], afh[im], bfh[in]);  // hi*hi
                    mma16(acc[im][in], afh[im], bfl[in]);  // hi*lo
                    mma16(acc[im][in], afl[im], bfh[in]);  // lo*hi
                }
        }
    }

    // ---- epilogue ----
    #pragma unroll
    for (int im = 0; im < MT; im++) {
        #pragma unroll
        for (int in = 0; in < NT2; in++) {
            const long row0 = rowBase + wm*WM + im*16 + r;
            const long row1 = row0 + 8;
            const int  col  = colBase + wn*WN + in*8 + 2*c;
            float2 d0 = make_float2(acc[im][in][0]*alpha, acc[im][in][1]*alpha);
            float2 d1 = make_float2(acc[im][in][2]*alpha, acc[im][in][3]*alpha);
            if (BIAS) {
                float2 bv = *(const float2*)(bias + col);
                d0.x += bv.x; d0.y += bv.y; d1.x += bv.x; d1.y += bv.y;
            }
            if (RES) {
                float2 r0 = *(const float2*)(res + row0*(long)ldc + col);
                float2 r1 = *(const float2*)(res + row1*(long)ldc + col);
                d0.x += r0.x; d0.y += r0.y; d1.x += r1.x; d1.y += r1.y;
            }
            if (RELU) {
                d0.x = fmaxf(d0.x, 0.f); d0.y = fmaxf(d0.y, 0.f);
                d1.x = fmaxf(d1.x, 0.f); d1.y = fmaxf(d1.y, 0.f);
            }
            if (OUTF) {
                *(float2*)(Cf + row0*(long)ldc + col) = d0;
                *(float2*)(Cf + row1*(long)ldc + col) = d1;
            }
            if (OUTB) {
                uint32_t hp, lp;
                bsplit2(d0.x, d0.y, hp, lp);
                *(uint32_t*)(Ch + row0*(long)ldc + col) = hp;
                *(uint32_t*)(Cl + row0*(long)ldc + col) = lp;
                bsplit2(d1.x, d1.y, hp, lp);
                *(uint32_t*)(Ch + row1*(long)ldc + col) = hp;
                *(uint32_t*)(Cl + row1*(long)ldc + col) = lp;
            }
        }
    }
}

// ---------------- split fp32 -> bf16 hi/lo pair ----------------
__global__ void split_k(const float* __restrict__ src,
                        bf16* __restrict__ dh, bf16* __restrict__ dl, long n)
{
    long i = ((long)blockIdx.x * blockDim.x + threadIdx.x) * 4;
    if (i < n) {
        float4 v = *(const float4*)(src + i);
        uint32_t h0,l0,h1,l1;
        bsplit2(v.x, v.y, h0, l0);
        bsplit2(v.z, v.w, h1, l1);
        uint32_t* ph = (uint32_t*)(dh + i);
        uint32_t* pl = (uint32_t*)(dl + i);
        ph[0] = h0; ph[1] = h1;
        pl[0] = l0; pl[1] = l1;
    }
}

// ---------------- transpose + split V: [B,S,H*64] -> [b*h][dh][S] -----------
__global__ void vtrans_k(const float* __restrict__ V,
                         bf16* __restrict__ Vth, bf16* __restrict__ Vtl)
{
    __shared__ float t[32][33];
    const int bh = blockIdx.z;
    const int b  = bh / HH, h = bh % HH;
    const int s0 = blockIdx.x * 32;
    const int d0 = blockIdx.y * 32;
    const int tx = threadIdx.x, ty = threadIdx.y;

    #pragma unroll
    for (int i = ty; i < 32; i += 8)
        t[i][tx] = V[((long)(b*SS + s0 + i))*DD + h*DHh + d0 + tx];
    __syncthreads();
    #pragma unroll
    for (int i = ty; i < 32; i += 8) {
        float v = t[tx][i];
        bf16 hb = __float2bfloat16(v);
        bf16 lb = __float2bfloat16(v - __bfloat162float(hb));
        long o = ((long)bh*DHh + d0 + i)*SS + s0 + tx;
        Vth[o] = hb; Vtl[o] = lb;
    }
}

// ---------------- softmax (len 2048), fp32 in -> bf16 hi/lo out -------------
__global__ void softmax_k(const float* __restrict__ Sc,
                          bf16* __restrict__ Sh, bf16* __restrict__ Sl)
{
    const long row = blockIdx.x;
    const float* p = Sc + row * (long)SS;
    const int tid = threadIdx.x;
    float4 v0 = ((const float4*)p)[tid];
    float4 v1 = ((const float4*)p)[tid + 256];

    float m = fmaxf(fmaxf(fmaxf(v0.x,v0.y), fmaxf(v0.z,v0.w)),
                    fmaxf(fmaxf(v1.x,v1.y), fmaxf(v1.z,v1.w)));
    #pragma unroll
    for (int o = 16; o; o >>= 1) m = fmaxf(m, __shfl_xor_sync(0xffffffffu, m, o));

    __shared__ float smax[8], ssum[8];
    const int wid = tid >> 5, lid = tid & 31;
    if (lid == 0) smax[wid] = m;
    __syncthreads();
    m = smax[0];
    #pragma unroll
    for (int i = 1; i < 8; i++) m = fmaxf(m, smax[i]);

    float e[8];
    e[0]=__expf(v0.x-m); e[1]=__expf(v0.y-m); e[2]=__expf(v0.z-m); e[3]=__expf(v0.w-m);
    e[4]=__expf(v1.x-m); e[5]=__expf(v1.y-m); e[6]=__expf(v1.z-m); e[7]=__expf(v1.w-m);
    float s = ((e[0]+e[1])+(e[2]+e[3])) + ((e[4]+e[5])+(e[6]+e[7]));
    #pragma unroll
    for (int o = 16; o; o >>= 1) s += __shfl_xor_sync(0xffffffffu, s, o);
    if (lid == 0) ssum[wid] = s;
    __syncthreads();
    s = ssum[0];
    #pragma unroll
    for (int i = 1; i < 8; i++) s += ssum[i];

    const float inv = 1.0f / s;
    uint32_t* ph = (uint32_t*)(Sh + row * (long)SS);
    uint32_t* pl = (uint32_t*)(Sl + row * (long)SS);
    uint32_t h,l;
    bsplit2(e[0]*inv, e[1]*inv, h, l); ph[tid*2    ] = h; pl[tid*2    ] = l;
    bsplit2(e[2]*inv, e[3]*inv, h, l); ph[tid*2 + 1] = h; pl[tid*2 + 1] = l;
    bsplit2(e[4]*inv, e[5]*inv, h, l); ph[512 + tid*2    ] = h; pl[512 + tid*2    ] = l;
    bsplit2(e[6]*inv, e[7]*inv, h, l); ph[512 + tid*2 + 1] = h; pl[512 + tid*2 + 1] = l;
}

// ---------------- layernorm (len 1024); fp32 out + optional bf16 pair -------
__global__ void ln_k(const float* __restrict__ in, float* __restrict__ out,
                     bf16* __restrict__ oh, bf16* __restrict__ ol,
                     const float* __restrict__ gw, const float* __restrict__ bw)
{
    const long row = blockIdx.x;
    const float* p = in + row * (long)DD;
    const int tid = threadIdx.x;
    float4 v = ((const float4*)p)[tid];
    float s = v.x + v.y + v.z + v.w;
    float q = v.x*v.x + v.y*v.y + v.z*v.z + v.w*v.w;
    #pragma unroll
    for (int o = 16; o; o >>= 1) {
        s += __shfl_xor_sync(0xffffffffu, s, o);
        q += __shfl_xor_sync(0xffffffffu, q, o);
    }
    __shared__ float ss[8], qq[8];
    const int wid = tid >> 5, lid = tid & 31;
    if (lid == 0) { ss[wid] = s; qq[wid] = q; }
    __syncthreads();
    float S = 0.f, Q = 0.f;
    #pragma unroll
    for (int i = 0; i < 8; i++) { S += ss[i]; Q += qq[i]; }

    const float mean = S * (1.0f / DD);
    const float var  = Q * (1.0f / DD) - mean * mean;
    const float inv  = rsqrtf(var + 1e-5f);

    float4 g4 = ((const float4*)gw)[tid];
    float4 b4 = ((const float4*)bw)[tid];
    float4 o;
    o.x = (v.x - mean) * inv * g4.x + b4.x;
    o.y = (v.y - mean) * inv * g4.y + b4.y;
    o.z = (v.z - mean) * inv * g4.z + b4.z;
    o.w = (v.w - mean) * inv * g4.w + b4.w;
    ((float4*)(out + row * (long)DD))[tid] = o;
    if (oh) {
        uint32_t h,l;
        uint32_t* ph = (uint32_t*)(oh + row * (long)DD);
        uint32_t* pl = (uint32_t*)(ol + row * (long)DD);
        bsplit2(o.x, o.y, h, l); ph[tid*2    ] = h; pl[tid*2    ] = l;
        bsplit2(o.z, o.w, h, l); ph[tid*2 + 1] = h; pl[tid*2 + 1] = l;
    }
}

// ---------------- launch ----------------
extern "C" void kernel_launch(void* const* d_in, const int* in_sizes, int n_in,
                              void* d_out, int out_size)
{
    const float* X   = (const float*)d_in[0];
    const float* Wq  = (const float*)d_in[1];
    const float* Wk  = (const float*)d_in[2];
    const float* Wo  = (const float*)d_in[3];
    const float* l1g = (const float*)d_in[4];
    const float* l1b = (const float*)d_in[5];
    const float* l2g = (const float*)d_in[6];
    const float* l2b = (const float*)d_in[7];
    const float* W1  = (const float*)d_in[8];
    const float* b1  = (const float*)d_in[9];
    const float* W2  = (const float*)d_in[10];
    const float* b2  = (const float*)d_in[11];
    float* out = (float*)d_out;

    float *V, *SCR, *Y;
    cudaGetSymbolAddress((void**)&V,   g_V);
    cudaGetSymbolAddress((void**)&SCR, g_scr);
    cudaGetSymbolAddress((void**)&Y,   g_Y);
    bf16 *Xh,*Xl,*Wqh,*Wql,*Wkh,*Wkl,*Woh,*Wol,*W1h,*W1l,*W2h,*W2l;
    bf16 *Qh,*Ql,*Kh,*Kl,*Vth,*Vtl,*Sch,*Scl,*CTh,*CTl,*Yh,*Yl;
    cudaGetSymbolAddress((void**)&Xh,  g_Xh);  cudaGetSymbolAddress((void**)&Xl,  g_Xl);
    cudaGetSymbolAddress((void**)&Wqh, g_Wqh); cudaGetSymbolAddress((void**)&Wql, g_Wql);
    cudaGetSymbolAddress((void**)&Wkh, g_Wkh); cudaGetSymbolAddress((void**)&Wkl, g_Wkl);
    cudaGetSymbolAddress((void**)&Woh, g_Woh); cudaGetSymbolAddress((void**)&Wol, g_Wol);
    cudaGetSymbolAddress((void**)&W1h, g_W1h); cudaGetSymbolAddress((void**)&W1l, g_W1l);
    cudaGetSymbolAddress((void**)&W2h, g_W2h); cudaGetSymbolAddress((void**)&W2l, g_W2l);
    cudaGetSymbolAddress((void**)&Qh,  g_Qh);  cudaGetSymbolAddress((void**)&Ql,  g_Ql);
    cudaGetSymbolAddress((void**)&Kh,  g_Kh);  cudaGetSymbolAddress((void**)&Kl,  g_Kl);
    cudaGetSymbolAddress((void**)&Vth, g_Vth); cudaGetSymbolAddress((void**)&Vtl, g_Vtl);
    cudaGetSymbolAddress((void**)&Sch, g_Sch); cudaGetSymbolAddress((void**)&Scl, g_Scl);
    cudaGetSymbolAddress((void**)&CTh, g_CTh); cudaGetSymbolAddress((void**)&CTl, g_CTl);
    cudaGetSymbolAddress((void**)&Yh,  g_Yh);  cudaGetSymbolAddress((void**)&Yl,  g_Yl);

    // aliased buffers (sequential lifetimes)
    float* Sc  = SCR;                       // attention scores chunk (fp32)
    bf16*  Hhh = (bf16*)SCR;                // FFN hidden hi (after attention done)
    bf16*  Hhl = Hhh + (long)BSR*FFD;       // FFN hidden lo
    float* AR  = V;                         // out-proj + residual (V dead after vtrans)
    float* Z   = V;                         // FFN2 out (AR dead after LN1)

    constexpr int SM128 = 2 * (2*128*20 + 2*128*20) * 4;   // 81920 B
    constexpr int SM64  = 2 * (2*128*20 + 2*64*20)  * 4;   // 61440 B
    cudaFuncSetAttribute(bg3<128,128,32,32,false,false,false,false,true>, cudaFuncAttributeMaxDynamicSharedMemorySize, SM128);
    cudaFuncSetAttribute(bg3<128,128,32,32,false,false,false,true,false>, cudaFuncAttributeMaxDynamicSharedMemorySize, SM128);
    cudaFuncSetAttribute(bg3<128,128,32,32,true ,false,false,true,false>, cudaFuncAttributeMaxDynamicSharedMemorySize, SM128);
    cudaFuncSetAttribute(bg3<128,64 ,32,16,false,false,false,false,true>, cudaFuncAttributeMaxDynamicSharedMemorySize, SM64);
    cudaFuncSetAttribute(bg3<128,128,32,32,false,false,true ,true,false>, cudaFuncAttributeMaxDynamicSharedMemorySize, SM128);
    cudaFuncSetAttribute(bg3<128,128,32,32,true ,true ,false,false,true>, cudaFuncAttributeMaxDynamicSharedMemorySize, SM128);
    cudaFuncSetAttribute(bg3<128,128,32,32,false,true ,true ,true,false>, cudaFuncAttributeMaxDynamicSharedMemorySize, SM128);

    const dim3 blk(512);
    const dim3 gproj(DD/128,  BSR/128, 1);
    const dim3 gscC (SS/128,  QC/128,  BB*HH);
    const dim3 gctxC(1,       QC/128,  BB*HH);
    const dim3 gf1  (FFD/128, BSR/128, 1);

    // --- pre-split inputs and weights to bf16 hi/lo ---
    split_k<<<(BSR*DD/4+255)/256, 256>>>(X,  Xh,  Xl,  (long)BSR*DD);
    split_k<<<(DD*DD/4 +255)/256, 256>>>(Wq, Wqh, Wql, (long)DD*DD);
    split_k<<<(DD*DD/4 +255)/256, 256>>>(Wk, Wkh, Wkl, (long)DD*DD);
    split_k<<<(DD*DD/4 +255)/256, 256>>>(Wo, Woh, Wol, (long)DD*DD);
    split_k<<<(FFD*DD/4+255)/256, 256>>>(W1, W1h, W1l, (long)FFD*DD);
    split_k<<<(DD*FFD/4+255)/256, 256>>>(W2, W2h, W2l, (long)DD*FFD);

    // --- QKV projections (Q,K -> bf16 pair; V -> fp32 for transpose) ---
    bg3<128,128,32,32,false,false,false,false,true><<<gproj, blk, SM128>>>(
        Xh, Xl, DD, Wqh, Wql, DD, nullptr, Qh, Ql, DD, DD, 1.f, nullptr, nullptr, 1, 0,0,0,0,0,0);
    bg3<128,128,32,32,false,false,false,false,true><<<gproj, blk, SM128>>>(
        Xh, Xl, DD, Wkh, Wkl, DD, nullptr, Kh, Kl, DD, DD, 1.f, nullptr, nullptr, 1, 0,0,0,0,0,0);
    bg3<128,128,32,32,false,false,false,true,false><<<gproj, blk, SM128>>>(
        Xh, Xl, DD, Woh, Wol, DD, V, nullptr, nullptr, DD, DD, 1.f, nullptr, nullptr, 1, 0,0,0,0,0,0);

    // --- transpose + split V ---
    vtrans_k<<<dim3(SS/32, DHh/32, BB*HH), dim3(32,8)>>>(V, Vth, Vtl);

    // --- attention, chunked over query rows ---
    for (int cch = 0; cch < NCHUNK; cch++) {
        bg3<128,128,32,32,true,false,false,true,false><<<gscC, blk, SM128>>>(
            Qh + (long)cch*QC*DD, Ql + (long)cch*QC*DD, DD,
            Kh, Kl, DD,
            Sc, nullptr, nullptr, SS, DHh, 0.125f, nullptr, nullptr,
            HH, (long)SS*DD, (long)DHh,
                (long)SS*DD, (long)DHh,
                (long)HH*QC*SS, (long)QC*SS);

        softmax_k<<<BB*HH*QC, 256>>>(Sc, Sch, Scl);

        // ctx chunk: attn[QC,S] @ Vt[b*H+h][DHh][S]^T   (correct batch offsets)
        bg3<128,64,32,16,false,false,false,false,true><<<gctxC, blk, SM64>>>(
            Sch, Scl, SS,
            Vth, Vtl, SS,
            nullptr, CTh + (long)cch*QC*DD, CTl + (long)cch*QC*DD, DD,
            SS, 1.f, nullptr, nullptr,
            HH, (long)HH*QC*SS, (long)QC*SS,
                (long)HH*DHh*SS, (long)DHh*SS,
                (long)SS*DD, (long)DHh);
    }

    // --- out-proj + residual X ---
    bg3<128,128,32,32,false,false,true,true,false><<<gproj, blk, SM128>>>(
        CTh, CTl, DD, Woh, Wol, DD, AR, nullptr, nullptr, DD, DD, 1.f, nullptr, X, 1, 0,0,0,0,0,0);

    // --- LN1 -> y (fp32 + pair) ---
    ln_k<<<BSR, 256>>>(AR, Y, Yh, Yl, l1g, l1b);

    // --- FFN1: relu(y @ W1^T + b1) -> bf16 pair hidden ---
    bg3<128,128,32,32,true,true,false,false,true><<<gf1, blk, SM128>>>(
        Yh, Yl, DD, W1h, W1l, DD, nullptr, Hhh, Hhl, FFD, DD, 1.f, b1, nullptr, 1, 0,0,0,0,0,0);

    // --- FFN2: h @ W2^T + b2 + y ---
    bg3<128,128,32,32,false,true,true,true,false><<<gproj, blk, SM128>>>(
        Hhh, Hhl, FFD, W2h, W2l, FFD, Z, nullptr, nullptr, DD, FFD, 1.f, b2, Y, 1, 0,0,0,0,0,0);

    // --- LN2 -> out ---
    ln_k<<<BSR, 256>>>(Z, out, nullptr, nullptr, l2g, l2b);
}

// round 15
// speedup vs baseline: 1.6636x; 1.6636x over previous
#include <cuda_runtime.h>
#include <cuda_bf16.h>
#include <cstdint>

// Problem constants
#define BB    2
#define SS    2048
#define DD    1024
#define HH    16
#define DHh   64
#define FFD   4096
#define BSR   (BB*SS)          // 4096 rows
#define QC    512              // query-chunk rows per attention pass
#define NCHUNK (SS/QC)         // 4

// ---------------- static scratch (~304MB; lifetimes sequential) -------------
__device__ float g_Q  [BB*SS*DD];          // 16 MB
__device__ float g_K  [BB*SS*DD];          // 16 MB
__device__ float g_V  [BB*SS*DD];          // 16 MB
__device__ float g_Vt [BB*HH*DHh*SS];      // 16 MB  V transposed [b*h][dh][S]
__device__ float g_Sc [BB*HH*QC*SS];       // 128 MB score chunk
__device__ float g_ctx[BB*SS*DD];          // 16 MB
__device__ float g_ar [BB*SS*DD];          // 16 MB
__device__ float g_y  [BB*SS*DD];          // 16 MB
__device__ float g_h  [BB*SS*FFD];         // 64 MB
__device__ float g_z  [BB*SS*DD];          // 16 MB

// ================= bf16 split helpers (R11-proven) =================
__device__ __forceinline__ void bsplit2(float x0, float x1, uint32_t& hp, uint32_t& lp)
{
    asm("cvt.rn.bf16x2.f32 %0, %1, %2;" : "=r"(hp) : "f"(x1), "f"(x0));
    float h0 = __uint_as_float(hp << 16);
    float h1 = __uint_as_float(hp & 0xffff0000u);
    float r0 = x0 - h0;
    float r1 = x1 - h1;
    asm("cvt.rn.bf16x2.f32 %0, %1, %2;" : "=r"(lp) : "f"(r1), "f"(r0));
}

__device__ __forceinline__ void mma16(float* d, const uint32_t* a, const uint32_t* b)
{
    asm volatile(
        "mma.sync.aligned.m16n8k16.row.col.f32.bf16.bf16.f32 "
        "{%0,%1,%2,%3},{%4,%5,%6,%7},{%8,%9},{%0,%1,%2,%3};"
        : "+f"(d[0]), "+f"(d[1]), "+f"(d[2]), "+f"(d[3])
        : "r"(a[0]), "r"(a[1]), "r"(a[2]), "r"(a[3]), "r"(b[0]), "r"(b[1]));
}

// ================= bf16-split NT GEMM (R11-proven, unchanged) =================
// C[M,N] = epilogue( alpha * A[M,K] @ B[N,K]^T ), fp32 in/out.
// 512 threads = 16 warps, warp grid (BM/WM)x(BN/WN) == 16.
// Smem: packed bf16x2 pairs, [row][pair] stride SDP=BK/2+4 (conflict-free LDS).
// Single smem buffer, register-staged prefetch (split happens once, at store).
template<int BM,int BN,int BK,int WM,int WN,bool RELU,bool BIAS,bool RES>
__global__ __launch_bounds__(512,1)
void bgemm_k(const float* __restrict__ A, int lda,
             const float* __restrict__ Bm, int ldb,
             float*       __restrict__ C,  int ldc,
             int K, float alpha,
             const float* __restrict__ bias,
             const float* __restrict__ res,
             int zdiv,
             long soA, long siA, long soB, long siB, long soC, long siC)
{
    constexpr int SDP = BK/2 + 4;          // uint32 pairs per row (stride 20 for BK=32)
    constexpr int MT  = WM / 16;
    constexpr int NT2 = WN / 8;
    constexpr int MW  = BM / WM;
    constexpr int KV  = BK / 4;
    constexpr int NAc = (BM * KV) / 512;   // float4 chunks per thread, A
    constexpr int NBc = (BN * KV) / 512;

    __shared__ uint32_t sAh[BM*SDP], sAl[BM*SDP];
    __shared__ uint32_t sBh[BN*SDP], sBl[BN*SDP];

    const int z  = blockIdx.z;
    const long zo = z / zdiv, zi = z % zdiv;
    A  += zo*soA + zi*siA;
    Bm += zo*soB + zi*siB;
    C  += zo*soC + zi*siC;

    const int tid    = threadIdx.x;
    const int lane   = tid & 31;
    const int warpId = tid >> 5;
    const int wm     = warpId % MW;
    const int wn     = warpId / MW;
    const int r      = lane >> 2;
    const int c      = lane & 3;
    const int rowBase = blockIdx.y * BM;
    const int colBase = blockIdx.x * BN;

    // per-thread tile-load coordinates (float4 chunks along K)
    int aR[NAc], aP[NAc];       // row, pair-base (chunk covers pairs aP, aP+1)
    #pragma unroll
    for (int j = 0; j < NAc; j++) {
        int i = tid + j*512;
        aR[j] = i / KV;
        aP[j] = (i % KV) * 2;
    }
    int bR[NBc], bP[NBc];
    #pragma unroll
    for (int j = 0; j < NBc; j++) {
        int i = tid + j*512;
        bR[j] = i / KV;
        bP[j] = (i % KV) * 2;
    }

    float acc[MT][NT2][4];
    #pragma unroll
    for (int im = 0; im < MT; im++)
        #pragma unroll
        for (int in = 0; in < NT2; in++)
            #pragma unroll
            for (int q = 0; q < 4; q++) acc[im][in][q] = 0.f;

    float4 ra[NAc], rb[NBc];
    const int nT = K / BK;

    // ---- prologue: load + split-store tile 0 ----
    #pragma unroll
    for (int j = 0; j < NAc; j++)
        ra[j] = *(const float4*)(A + (long)(rowBase + aR[j])*lda + aP[j]*2);
    #pragma unroll
    for (int j = 0; j < NBc; j++)
        rb[j] = *(const float4*)(Bm + (long)(colBase + bR[j])*ldb + bP[j]*2);
    #pragma unroll
    for (int j = 0; j < NAc; j++) {
        uint32_t h0,l0,h1,l1;
        bsplit2(ra[j].x, ra[j].y, h0, l0);
        bsplit2(ra[j].z, ra[j].w, h1, l1);
        sAh[aR[j]*SDP + aP[j]    ] = h0;  sAl[aR[j]*SDP + aP[j]    ] = l0;
        sAh[aR[j]*SDP + aP[j] + 1] = h1;  sAl[aR[j]*SDP + aP[j] + 1] = l1;
    }
    #pragma unroll
    for (int j = 0; j < NBc; j++) {
        uint32_t h0,l0,h1,l1;
        bsplit2(rb[j].x, rb[j].y, h0, l0);
        bsplit2(rb[j].z, rb[j].w, h1, l1);
        sBh[bR[j]*SDP + bP[j]    ] = h0;  sBl[bR[j]*SDP + bP[j]    ] = l0;
        sBh[bR[j]*SDP + bP[j] + 1] = h1;  sBl[bR[j]*SDP + bP[j] + 1] = l1;
    }
    __syncthreads();

    for (int t = 0; t < nT; t++) {
        const bool has_next = (t + 1) < nT;
        // prefetch next tile into registers (overlaps compute)
        if (has_next) {
            const int kn = (t + 1) * BK;
            #pragma unroll
            for (int j = 0; j < NAc; j++)
                ra[j] = *(const float4*)(A + (long)(rowBase + aR[j])*lda + (kn + aP[j]*2));
            #pragma unroll
            for (int j = 0; j < NBc; j++)
                rb[j] = *(const float4*)(Bm + (long)(colBase + bR[j])*ldb + (kn + bP[j]*2));
        }

        // compute: BK/16 ksteps of m16n8k16, 3-MMA split each
        #pragma unroll
        for (int ks = 0; ks < BK/16; ks++) {
            const int pb = ks * 8;     // pair base of this kstep
            uint32_t afh[MT][4], afl[MT][4], bfh[NT2][2], bfl[NT2][2];
            #pragma unroll
            for (int im = 0; im < MT; im++) {
                const int mb = wm*WM + im*16;
                afh[im][0] = sAh[(mb+r  )*SDP + pb + c    ];
                afh[im][1] = sAh[(mb+r+8)*SDP + pb + c    ];
                afh[im][2] = sAh[(mb+r  )*SDP + pb + c + 4];
                afh[im][3] = sAh[(mb+r+8)*SDP + pb + c + 4];
                afl[im][0] = sAl[(mb+r  )*SDP + pb + c    ];
                afl[im][1] = sAl[(mb+r+8)*SDP + pb + c    ];
                afl[im][2] = sAl[(mb+r  )*SDP + pb + c + 4];
                afl[im][3] = sAl[(mb+r+8)*SDP + pb + c + 4];
            }
            #pragma unroll
            for (int in = 0; in < NT2; in++) {
                const int nb = wn*WN + in*8;
                bfh[in][0] = sBh[(nb+r)*SDP + pb + c    ];
                bfh[in][1] = sBh[(nb+r)*SDP + pb + c + 4];
                bfl[in][0] = sBl[(nb+r)*SDP + pb + c    ];
                bfl[in][1] = sBl[(nb+r)*SDP + pb + c + 4];
            }
            #pragma unroll
            for (int im = 0; im < MT; im++)
                #pragma unroll
                for (int in = 0; in < NT2; in++) {
                    mma16(acc[im][in], afh[im], bfh[in]);  // hi*hi
                    mma16(acc[im][in], afh[im], bfl[in]);  // hi*lo
                    mma16(acc[im][in], afl[im], bfh[in]);  // lo*hi
                }
        }
        __syncthreads();

        if (has_next) {
            #pragma unroll
            for (int j = 0; j < NAc; j++) {
                uint32_t h0,l0,h1,l1;
                bsplit2(ra[j].x, ra[j].y, h0, l0);
                bsplit2(ra[j].z, ra[j].w, h1, l1);
                sAh[aR[j]*SDP + aP[j]    ] = h0;  sAl[aR[j]*SDP + aP[j]    ] = l0;
                sAh[aR[j]*SDP + aP[j] + 1] = h1;  sAl[aR[j]*SDP + aP[j] + 1] = l1;
            }
            #pragma unroll
            for (int j = 0; j < NBc; j++) {
                uint32_t h0,l0,h1,l1;
                bsplit2(rb[j].x, rb[j].y, h0, l0);
                bsplit2(rb[j].z, rb[j].w, h1, l1);
                sBh[bR[j]*SDP + bP[j]    ] = h0;  sBl[bR[j]*SDP + bP[j]    ] = l0;
                sBh[bR[j]*SDP + bP[j] + 1] = h1;  sBl[bR[j]*SDP + bP[j] + 1] = l1;
            }
            __syncthreads();
        }
    }

    // ---- epilogue ----
    #pragma unroll
    for (int im = 0; im < MT; im++) {
        #pragma unroll
        for (int in = 0; in < NT2; in++) {
            const long row0 = rowBase + wm*WM + im*16 + r;
            const long row1 = row0 + 8;
            const int  col  = colBase + wn*WN + in*8 + 2*c;
            float2 d0 = make_float2(acc[im][in][0]*alpha, acc[im][in][1]*alpha);
            float2 d1 = make_float2(acc[im][in][2]*alpha, acc[im][in][3]*alpha);
            if (BIAS) {
                float2 bv = *(const float2*)(bias + col);
                d0.x += bv.x; d0.y += bv.y; d1.x += bv.x; d1.y += bv.y;
            }
            if (RES) {
                float2 r0 = *(const float2*)(res + row0*(long)ldc + col);
                float2 r1 = *(const float2*)(res + row1*(long)ldc + col);
                d0.x += r0.x; d0.y += r0.y; d1.x += r1.x; d1.y += r1.y;
            }
            if (RELU) {
                d0.x = fmaxf(d0.x, 0.f); d0.y = fmaxf(d0.y, 0.f);
                d1.x = fmaxf(d1.x, 0.f); d1.y = fmaxf(d1.y, 0.f);
            }
            *(float2*)(C + row0*(long)ldc + col) = d0;
            *(float2*)(C + row1*(long)ldc + col) = d1;
        }
    }
}

// ---------------- transpose V (fp32, exact): [B,S,H*64] -> [b*h][dh][S] -----
__global__ void vtrans_k(const float* __restrict__ V, float* __restrict__ Vt)
{
    __shared__ float t[32][33];
    const int bh = blockIdx.z;
    const int b  = bh / HH, h = bh % HH;
    const int s0 = blockIdx.x * 32;
    const int d0 = blockIdx.y * 32;
    const int tx = threadIdx.x, ty = threadIdx.y;

    #pragma unroll
    for (int i = ty; i < 32; i += 8)
        t[i][tx] = V[((long)(b*SS + s0 + i))*DD + h*DHh + d0 + tx];
    __syncthreads();
    #pragma unroll
    for (int i = ty; i < 32; i += 8)
        Vt[((long)bh*DHh + d0 + i)*SS + s0 + tx] = t[tx][i];
}

// ---------------- softmax over rows of length 2048 (input already relu'd) ----
__global__ void softmax_k(float* __restrict__ Sc)
{
    const long row = blockIdx.x;
    float* p = Sc + row * (long)SS;
    const int tid = threadIdx.x;
    float4 v0 = ((const float4*)p)[tid];
    float4 v1 = ((const float4*)p)[tid + 256];

    float m = fmaxf(fmaxf(fmaxf(v0.x,v0.y), fmaxf(v0.z,v0.w)),
                    fmaxf(fmaxf(v1.x,v1.y), fmaxf(v1.z,v1.w)));
    #pragma unroll
    for (int o = 16; o; o >>= 1) m = fmaxf(m, __shfl_xor_sync(0xffffffffu, m, o));

    __shared__ float smax[8], ssum[8];
    const int wid = tid >> 5, lid = tid & 31;
    if (lid == 0) smax[wid] = m;
    __syncthreads();
    m = smax[0];
    #pragma unroll
    for (int i = 1; i < 8; i++) m = fmaxf(m, smax[i]);

    float e[8];
    e[0]=__expf(v0.x-m); e[1]=__expf(v0.y-m); e[2]=__expf(v0.z-m); e[3]=__expf(v0.w-m);
    e[4]=__expf(v1.x-m); e[5]=__expf(v1.y-m); e[6]=__expf(v1.z-m); e[7]=__expf(v1.w-m);
    float s = ((e[0]+e[1])+(e[2]+e[3])) + ((e[4]+e[5])+(e[6]+e[7]));
    #pragma unroll
    for (int o = 16; o; o >>= 1) s += __shfl_xor_sync(0xffffffffu, s, o);
    if (lid == 0) ssum[wid] = s;
    __syncthreads();
    s = ssum[0];
    #pragma unroll
    for (int i = 1; i < 8; i++) s += ssum[i];

    const float inv = 1.0f / s;
    ((float4*)p)[tid]       = make_float4(e[0]*inv, e[1]*inv, e[2]*inv, e[3]*inv);
    ((float4*)p)[tid + 256] = make_float4(e[4]*inv, e[5]*inv, e[6]*inv, e[7]*inv);
}

// ---------------- layernorm over rows of length 1024 ----------------
__global__ void ln_k(const float* __restrict__ in, float* __restrict__ out,
                     const float* __restrict__ gw, const float* __restrict__ bw)
{
    const long row = blockIdx.x;
    const float* p = in + row * (long)DD;
    const int tid = threadIdx.x;
    float4 v = ((const float4*)p)[tid];
    float s = v.x + v.y + v.z + v.w;
    float q = v.x*v.x + v.y*v.y + v.z*v.z + v.w*v.w;
    #pragma unroll
    for (int o = 16; o; o >>= 1) {
        s += __shfl_xor_sync(0xffffffffu, s, o);
        q += __shfl_xor_sync(0xffffffffu, q, o);
    }
    __shared__ float ss[8], qq[8];
    const int wid = tid >> 5, lid = tid & 31;
    if (lid == 0) { ss[wid] = s; qq[wid] = q; }
    __syncthreads();
    float S = 0.f, Q = 0.f;
    #pragma unroll
    for (int i = 0; i < 8; i++) { S += ss[i]; Q += qq[i]; }

    const float mean = S * (1.0f / DD);
    const float var  = Q * (1.0f / DD) - mean * mean;
    const float inv  = rsqrtf(var + 1e-5f);

    float4 g4 = ((const float4*)gw)[tid];
    float4 b4 = ((const float4*)bw)[tid];
    float4 o;
    o.x = (v.x - mean) * inv * g4.x + b4.x;
    o.y = (v.y - mean) * inv * g4.y + b4.y;
    o.z = (v.z - mean) * inv * g4.z + b4.z;
    o.w = (v.w - mean) * inv * g4.w + b4.w;
    ((float4*)(out + row * (long)DD))[tid] = o;
}

// ---------------- launch ----------------
extern "C" void kernel_launch(void* const* d_in, const int* in_sizes, int n_in,
                              void* d_out, int out_size)
{
    const float* X   = (const float*)d_in[0];
    const float* Wq  = (const float*)d_in[1];
    const float* Wk  = (const float*)d_in[2];
    const float* Wo  = (const float*)d_in[3];
    const float* l1g = (const float*)d_in[4];
    const float* l1b = (const float*)d_in[5];
    const float* l2g = (const float*)d_in[6];
    const float* l2b = (const float*)d_in[7];
    const float* W1  = (const float*)d_in[8];
    const float* b1  = (const float*)d_in[9];
    const float* W2  = (const float*)d_in[10];
    const float* b2  = (const float*)d_in[11];
    float* out = (float*)d_out;

    float *Q, *K, *V, *Vt, *Sc, *CT, *AR, *Y, *Hh, *Z;
    cudaGetSymbolAddress((void**)&Q,  g_Q);
    cudaGetSymbolAddress((void**)&K,  g_K);
    cudaGetSymbolAddress((void**)&V,  g_V);
    cudaGetSymbolAddress((void**)&Vt, g_Vt);
    cudaGetSymbolAddress((void**)&Sc, g_Sc);
    cudaGetSymbolAddress((void**)&CT, g_ctx);
    cudaGetSymbolAddress((void**)&AR, g_ar);
    cudaGetSymbolAddress((void**)&Y,  g_y);
    cudaGetSymbolAddress((void**)&Hh, g_h);
    cudaGetSymbolAddress((void**)&Z,  g_z);

    const dim3 blk512(512);
    const dim3 gproj(DD/128,  BSR/128, 1);
    const dim3 gscC (SS/128,  QC/128,  BB*HH);   // 16 x 4 x 32 = 2048 CTAs
    const dim3 gctxC(1,       QC/128,  BB*HH);   // 1 x 4 x 32 = 128 CTAs
    const dim3 gf1  (FFD/128, BSR/128, 1);

    // --- QKV projections: Q/K = X@Wq^T / X@Wk^T, V = X@Wo^T ---
    bgemm_k<128,128,32,32,32,false,false,false><<<gproj, blk512>>>(
        X, DD, Wq, DD, Q, DD, DD, 1.f, nullptr, nullptr, 1, 0,0,0,0,0,0);
    bgemm_k<128,128,32,32,32,false,false,false><<<gproj, blk512>>>(
        X, DD, Wk, DD, K, DD, DD, 1.f, nullptr, nullptr, 1, 0,0,0,0,0,0);
    bgemm_k<128,128,32,32,32,false,false,false><<<gproj, blk512>>>(
        X, DD, Wo, DD, V, DD, DD, 1.f, nullptr, nullptr, 1, 0,0,0,0,0,0);

    // --- transpose V for NT ctx ---
    vtrans_k<<<dim3(SS/32, DHh/32, BB*HH), dim3(32,8)>>>(V, Vt);

    // --- attention, chunked over query rows ---
    for (int cch = 0; cch < NCHUNK; cch++) {
        // scores chunk: relu(Q[c] @ K^T / 8), batched over (b,h)
        bgemm_k<128,128,32,32,32,true,false,false><<<gscC, blk512>>>(
            Q + (long)cch*QC*DD, DD, K, DD, Sc, SS, DHh, 0.125f, nullptr, nullptr,
            HH, (long)SS*DD, (long)DHh,
                (long)SS*DD, (long)DHh,
                (long)HH*QC*SS, (long)QC*SS);

        softmax_k<<<BB*HH*QC, 256>>>(Sc);

        // ctx chunk = attn[QC,S] @ Vt[b*H+h][dh][S]^T  (bf16-split NT gemm)
        bgemm_k<128,64,32,32,16,false,false,false><<<gctxC, blk512>>>(
            Sc, SS, Vt, SS, CT + (long)cch*QC*DD, DD, SS, 1.f, nullptr, nullptr,
            HH, (long)HH*QC*SS, (long)QC*SS,
                (long)HH*DHh*SS, (long)DHh*SS,
                (long)SS*DD, (long)DHh);
    }

    // --- out-proj + residual X ---
    bgemm_k<128,128,32,32,32,false,false,true><<<gproj, blk512>>>(
        CT, DD, Wo, DD, AR, DD, DD, 1.f, nullptr, X, 1, 0,0,0,0,0,0);

    ln_k<<<BSR, 256>>>(AR, Y, l1g, l1b);

    // --- FFN1: relu(y @ W1^T + b1) ---
    bgemm_k<128,128,32,32,32,true,true,false><<<gf1, blk512>>>(
        Y, DD, W1, DD, Hh, FFD, DD, 1.f, b1, nullptr, 1, 0,0,0,0,0,0);

    // --- FFN2: h @ W2^T + b2 + y ---
    bgemm_k<128,128,32,32,32,false,true,true><<<gproj, blk512>>>(
        Hh, FFD, W2, FFD, Z, DD, FFD, 1.f, b2, Y, 1, 0,0,0,0,0,0);

    ln_k<<<BSR, 256>>>(Z, out, l2g, l2b);
}